// round 1
// baseline (speedup 1.0000x reference)
#include <cuda_runtime.h>
#include <math.h>

// Problem constants
// B=128, NQ=NK=64, D_IN=1024, H=16, DK=DV=64, E=H*DK=1024, D_OUT=1024
#define NBATCH   128
#define NPOS     64
#define DIN      1024
#define NHEAD    16
#define DHEAD    64
#define EDIM     1024
#define DOUT     1024
#define OUT_ELEMS (NBATCH * NPOS * DOUT)         // 8388608
#define ATTN_ELEMS (NBATCH * NHEAD * NPOS * NPOS) // 8388608

// Scratch (allocation-free: __device__ globals)
__device__ float g_qp[NBATCH * NPOS * EDIM];
__device__ float g_kp[NBATCH * NPOS * EDIM];
__device__ float g_vp[NBATCH * NPOS * EDIM];
__device__ float g_ctx[NBATCH * NPOS * EDIM];

// ---------------------------------------------------------------------------
// Grouped projection GEMM.
// For group g (position n in [0,64)):
//   C[b, e] = sum_d X[b, g, d] * W[g, d, e]
// X layout [B, 64, 1024]: A(m=b, k=d) at X[(m*64 + g)*1024 + k]  (lda = 65536)
// W layout [64, 1024, 1024]: W[g*1048576 + k*1024 + n]
// C same layout as X.
// Tile: BM=64, BN=64, BK=16, 256 threads, 4x4 microtile per thread.
// ---------------------------------------------------------------------------
__global__ void __launch_bounds__(256) proj_gemm(
    const float* __restrict__ X, const float* __restrict__ W, float* __restrict__ C)
{
    const int g = blockIdx.z;
    const int mBase = blockIdx.y * 64;
    const int nBase = blockIdx.x * 64;

    const float* Ag = X + (long)g * 1024;
    const float* Wg = W + (long)g * 1048576;
    float* Cg = C + (long)g * 1024;

    __shared__ float As[16][64];
    __shared__ float Bs[16][64];

    const int tid = threadIdx.x;
    const int tx = tid & 15;   // 0..15 (n direction)
    const int ty = tid >> 4;   // 0..15 (m direction)
    const int alr = tid >> 2;  // A load row 0..63
    const int alc = tid & 3;   // A load col4 0..3
    const int blr = tid >> 4;  // B load k-row 0..15
    const int blc = tid & 15;  // B load col4 0..15

    float acc[4][4] = {};

    for (int k0 = 0; k0 < 1024; k0 += 16) {
        float4 av = *(const float4*)(Ag + (long)(mBase + alr) * 65536 + k0 + alc * 4);
        float4 bv = *(const float4*)(Wg + (long)(k0 + blr) * 1024 + nBase + blc * 4);
        As[alc * 4 + 0][alr] = av.x;
        As[alc * 4 + 1][alr] = av.y;
        As[alc * 4 + 2][alr] = av.z;
        As[alc * 4 + 3][alr] = av.w;
        *(float4*)&Bs[blr][blc * 4] = bv;
        __syncthreads();
#pragma unroll
        for (int kk = 0; kk < 16; kk++) {
            float4 a4 = *(const float4*)&As[kk][ty * 4];
            float4 b4 = *(const float4*)&Bs[kk][tx * 4];
            float a[4] = {a4.x, a4.y, a4.z, a4.w};
            float b[4] = {b4.x, b4.y, b4.z, b4.w};
#pragma unroll
            for (int i = 0; i < 4; i++)
#pragma unroll
                for (int j = 0; j < 4; j++)
                    acc[i][j] = fmaf(a[i], b[j], acc[i][j]);
        }
        __syncthreads();
    }

#pragma unroll
    for (int i = 0; i < 4; i++) {
        float4 o = make_float4(acc[i][0], acc[i][1], acc[i][2], acc[i][3]);
        *(float4*)(Cg + (long)(mBase + ty * 4 + i) * 65536 + nBase + tx * 4) = o;
    }
}

// ---------------------------------------------------------------------------
// Attention kernel: one CTA per (b, h). 2048 CTAs, 256 threads.
// Loads Q,K tiles [64 x 64] into smem, computes scores in registers (4x4 per
// thread), softmax via 16-lane shuffle groups, writes attn to d_out tail and
// into smem, loads V into (reused) K smem, computes context, writes g_ctx.
// ---------------------------------------------------------------------------
__global__ void __launch_bounds__(256) attn_kernel(
    const float* __restrict__ qp, const float* __restrict__ kp,
    const float* __restrict__ vp, float* __restrict__ attn_out,
    float* __restrict__ ctx)
{
    __shared__ float qs[64][65];
    __shared__ float ks[64][65];

    const int bh = blockIdx.x;
    const int b = bh >> 4;
    const int h = bh & 15;
    const int tid = threadIdx.x;
    const int tx = tid & 15;
    const int ty = tid >> 4;

    const float* qbase = qp + (long)(b * 64) * 1024 + h * 64;
    const float* kbase = kp + (long)(b * 64) * 1024 + h * 64;

    // cooperative load Q, K tiles (each 64x64 floats = 1024 float4s)
#pragma unroll
    for (int i = 0; i < 4; i++) {
        int f = i * 256 + tid;
        int row = f >> 4;
        int c4 = f & 15;
        float4 v = *(const float4*)(qbase + (long)row * 1024 + c4 * 4);
        qs[row][c4 * 4 + 0] = v.x; qs[row][c4 * 4 + 1] = v.y;
        qs[row][c4 * 4 + 2] = v.z; qs[row][c4 * 4 + 3] = v.w;
        float4 w = *(const float4*)(kbase + (long)row * 1024 + c4 * 4);
        ks[row][c4 * 4 + 0] = w.x; ks[row][c4 * 4 + 1] = w.y;
        ks[row][c4 * 4 + 2] = w.z; ks[row][c4 * 4 + 3] = w.w;
    }
    __syncthreads();

    // scores s[q][k], q = ty*4+i, k = tx*4+j
    float s[4][4] = {};
#pragma unroll 8
    for (int d = 0; d < 64; d++) {
        float a[4], bb[4];
#pragma unroll
        for (int i = 0; i < 4; i++) a[i] = qs[ty * 4 + i][d];
#pragma unroll
        for (int j = 0; j < 4; j++) bb[j] = ks[tx * 4 + j][d];
#pragma unroll
        for (int i = 0; i < 4; i++)
#pragma unroll
            for (int j = 0; j < 4; j++)
                s[i][j] = fmaf(a[i], bb[j], s[i][j]);
    }
    __syncthreads();  // all reads of qs/ks done before reuse

    // softmax per row (each row spans 16 lanes x 4 cols); lanes with the same
    // ty form a contiguous 16-lane group inside one warp.
    float a[4][4];
#pragma unroll
    for (int i = 0; i < 4; i++) {
        float m = -1e30f;
#pragma unroll
        for (int j = 0; j < 4; j++) {
            s[i][j] *= 0.125f;  // 1/sqrt(DK)
            m = fmaxf(m, s[i][j]);
        }
#pragma unroll
        for (int off = 8; off >= 1; off >>= 1)
            m = fmaxf(m, __shfl_xor_sync(0xffffffffu, m, off));
        float sum = 0.f;
#pragma unroll
        for (int j = 0; j < 4; j++) {
            a[i][j] = __expf(s[i][j] - m);
            sum += a[i][j];
        }
#pragma unroll
        for (int off = 8; off >= 1; off >>= 1)
            sum += __shfl_xor_sync(0xffffffffu, sum, off);
        float inv = 1.f / sum;
#pragma unroll
        for (int j = 0; j < 4; j++) a[i][j] *= inv;
    }

    // store attn into qs (reused) + global attn output [B,H,NQ,NK]
    float* aout = attn_out + ((long)(b * 16 + h) * 64) * 64;
#pragma unroll
    for (int i = 0; i < 4; i++) {
#pragma unroll
        for (int j = 0; j < 4; j++) qs[ty * 4 + i][tx * 4 + j] = a[i][j];
        float4 o = make_float4(a[i][0], a[i][1], a[i][2], a[i][3]);
        *(float4*)(aout + (ty * 4 + i) * 64 + tx * 4) = o;
    }

    // load V into ks (reused)
    const float* vbase = vp + (long)(b * 64) * 1024 + h * 64;
#pragma unroll
    for (int i = 0; i < 4; i++) {
        int f = i * 256 + tid;
        int row = f >> 4;
        int c4 = f & 15;
        float4 v = *(const float4*)(vbase + (long)row * 1024 + c4 * 4);
        ks[row][c4 * 4 + 0] = v.x; ks[row][c4 * 4 + 1] = v.y;
        ks[row][c4 * 4 + 2] = v.z; ks[row][c4 * 4 + 3] = v.w;
    }
    __syncthreads();

    // context: out[q][d] = sum_k attn[q][k] * V[k][d]
    float o[4][4] = {};
#pragma unroll 8
    for (int k = 0; k < 64; k++) {
        float av[4], bv[4];
#pragma unroll
        for (int i = 0; i < 4; i++) av[i] = qs[ty * 4 + i][k];
#pragma unroll
        for (int j = 0; j < 4; j++) bv[j] = ks[k][tx * 4 + j];
#pragma unroll
        for (int i = 0; i < 4; i++)
#pragma unroll
            for (int j = 0; j < 4; j++)
                o[i][j] = fmaf(av[i], bv[j], o[i][j]);
    }

    float* cb = ctx + (long)(b * 64) * 1024 + h * 64;
#pragma unroll
    for (int i = 0; i < 4; i++) {
        float4 v = make_float4(o[i][0], o[i][1], o[i][2], o[i][3]);
        *(float4*)(cb + (long)(ty * 4 + i) * 1024 + tx * 4) = v;
    }
}

// ---------------------------------------------------------------------------
// Fused fc + gate GEMM with sigmoid*tanh epilogue.
// A = ctx [8192, 1024] row-major; fcw/gw [1024(out), 1024(in)] row-major.
// out[m, n] = sigmoid(sum_e A[m,e]*gw[n,e] + gb[n]) * tanh(sum_e A[m,e]*fcw[n,e] + fb[n])
// Tile BM=64, BN=64, BK=16, 256 threads, dual 4x4 microtiles.
// ---------------------------------------------------------------------------
__global__ void __launch_bounds__(256) fc_gate_kernel(
    const float* __restrict__ A, const float* __restrict__ fcw,
    const float* __restrict__ fb, const float* __restrict__ gw,
    const float* __restrict__ gb, float* __restrict__ out)
{
    __shared__ float As[16][64];
    __shared__ float Bf[16][64];
    __shared__ float Bg[16][64];

    const int mBase = blockIdx.y * 64;
    const int nBase = blockIdx.x * 64;
    const int tid = threadIdx.x;
    const int tx = tid & 15;
    const int ty = tid >> 4;
    const int lr = tid >> 2;  // load row 0..63
    const int lc = tid & 3;   // load col4 0..3

    float accF[4][4] = {};
    float accG[4][4] = {};

    for (int k0 = 0; k0 < 1024; k0 += 16) {
        float4 av = *(const float4*)(A + (long)(mBase + lr) * 1024 + k0 + lc * 4);
        float4 fv = *(const float4*)(fcw + (long)(nBase + lr) * 1024 + k0 + lc * 4);
        float4 gv = *(const float4*)(gw + (long)(nBase + lr) * 1024 + k0 + lc * 4);
        As[lc * 4 + 0][lr] = av.x; As[lc * 4 + 1][lr] = av.y;
        As[lc * 4 + 2][lr] = av.z; As[lc * 4 + 3][lr] = av.w;
        Bf[lc * 4 + 0][lr] = fv.x; Bf[lc * 4 + 1][lr] = fv.y;
        Bf[lc * 4 + 2][lr] = fv.z; Bf[lc * 4 + 3][lr] = fv.w;
        Bg[lc * 4 + 0][lr] = gv.x; Bg[lc * 4 + 1][lr] = gv.y;
        Bg[lc * 4 + 2][lr] = gv.z; Bg[lc * 4 + 3][lr] = gv.w;
        __syncthreads();
#pragma unroll
        for (int kk = 0; kk < 16; kk++) {
            float4 a4 = *(const float4*)&As[kk][ty * 4];
            float4 f4 = *(const float4*)&Bf[kk][tx * 4];
            float4 g4 = *(const float4*)&Bg[kk][tx * 4];
            float a[4] = {a4.x, a4.y, a4.z, a4.w};
            float f[4] = {f4.x, f4.y, f4.z, f4.w};
            float g[4] = {g4.x, g4.y, g4.z, g4.w};
#pragma unroll
            for (int i = 0; i < 4; i++)
#pragma unroll
                for (int j = 0; j < 4; j++) {
                    accF[i][j] = fmaf(a[i], f[j], accF[i][j]);
                    accG[i][j] = fmaf(a[i], g[j], accG[i][j]);
                }
        }
        __syncthreads();
    }

#pragma unroll
    for (int i = 0; i < 4; i++) {
        float vals[4];
#pragma unroll
        for (int j = 0; j < 4; j++) {
            int n = nBase + tx * 4 + j;
            float f = accF[i][j] + fb[n];
            float gv2 = accG[i][j] + gb[n];
            float sg = 1.f / (1.f + __expf(-gv2));
            vals[j] = sg * tanhf(f);
        }
        float4 o = make_float4(vals[0], vals[1], vals[2], vals[3]);
        *(float4*)(out + (long)(mBase + ty * 4 + i) * 1024 + nBase + tx * 4) = o;
    }
}

// ---------------------------------------------------------------------------
// Launch
// ---------------------------------------------------------------------------
extern "C" void kernel_launch(void* const* d_in, const int* in_sizes, int n_in,
                              void* d_out, int out_size) {
    const float* q    = (const float*)d_in[0];
    const float* k    = (const float*)d_in[1];
    const float* v    = (const float*)d_in[2];
    const float* w_q  = (const float*)d_in[3];
    const float* w_k  = (const float*)d_in[4];
    const float* w_v  = (const float*)d_in[5];
    const float* fc_w = (const float*)d_in[6];
    const float* fc_b = (const float*)d_in[7];
    const float* g_w  = (const float*)d_in[8];
    const float* g_b  = (const float*)d_in[9];

    float* out = (float*)d_out;                 // [B, NQ, DOUT]
    float* attn = (float*)d_out + OUT_ELEMS;    // [B, H, NQ, NK]

    float *qp, *kp, *vp, *ctx;
    cudaGetSymbolAddress((void**)&qp, g_qp);
    cudaGetSymbolAddress((void**)&kp, g_kp);
    cudaGetSymbolAddress((void**)&vp, g_vp);
    cudaGetSymbolAddress((void**)&ctx, g_ctx);

    dim3 gp(16, 2, 64);  // N tiles, M tiles, groups
    proj_gemm<<<gp, 256>>>(q, w_q, qp);
    proj_gemm<<<gp, 256>>>(k, w_k, kp);
    proj_gemm<<<gp, 256>>>(v, w_v, vp);

    attn_kernel<<<2048, 256>>>(qp, kp, vp, attn, ctx);

    dim3 gf(16, 128);  // N tiles (1024/64), M tiles (8192/64)
    fc_gate_kernel<<<gf, 256>>>(ctx, fc_w, fc_b, g_w, g_b, out);
}

// round 6
// speedup vs baseline: 2.5503x; 2.5503x over previous
#include <cuda_runtime.h>
#include <cstdint>
#include <math.h>

// B=128, NQ=NK=64, D_IN=1024, H=16, DK=DV=64, E=1024, D_OUT=1024
#define OUT_ELEMS (128 * 64 * 1024)

// Scratch (allocation-free)
__device__ float g_qp[128 * 64 * 1024];   // q proj; reused as tanh(fc) scratch later
__device__ float g_kp[128 * 64 * 1024];
__device__ float g_vp[128 * 64 * 1024];
__device__ float g_ctx[128 * 64 * 1024];

__device__ __forceinline__ float tf32r(float x) {
    float r; asm("cvt.rna.tf32.f32 %0, %1;" : "=f"(r) : "f"(x)); return r;
}

// D += A*B  (m16n8k8 tf32, row.col)
__device__ __forceinline__ void mma8(float* d, const uint32_t* a, const uint32_t* b) {
    asm volatile(
        "mma.sync.aligned.m16n8k8.row.col.f32.tf32.tf32.f32 "
        "{%0,%1,%2,%3},{%4,%5,%6,%7},{%8,%9},{%0,%1,%2,%3};"
        : "+f"(d[0]), "+f"(d[1]), "+f"(d[2]), "+f"(d[3])
        : "r"(a[0]), "r"(a[1]), "r"(a[2]), "r"(a[3]), "r"(b[0]), "r"(b[1]));
}

// SMEM: per stage, A tile 128x32 floats stride 36 (4608 f), B tile same.
// stage s base: s*9216 floats. A at +0, B at +4608.
#define ASTRIDE 36
#define STAGE_F 9216

// Fragment LDS + MMA over one 32-K slab. acc[2][8][4].
#define GEMM_COMPUTE(sbase)                                                     \
    do {                                                                        \
        const float* aS = sm + (sbase);                                         \
        const float* bS = aS + 4608;                                            \
        _Pragma("unroll") for (int kk = 0; kk < 4; kk++) {                      \
            uint32_t af[2][4], bf[8][2];                                        \
            _Pragma("unroll") for (int mt = 0; mt < 2; mt++) {                  \
                int row = wm * 32 + mt * 16 + (lane >> 2);                      \
                int col = kk * 8 + (lane & 3);                                  \
                af[mt][0] = __float_as_uint(aS[row * ASTRIDE + col]);           \
                af[mt][1] = __float_as_uint(aS[(row + 8) * ASTRIDE + col]);     \
                af[mt][2] = __float_as_uint(aS[row * ASTRIDE + col + 4]);       \
                af[mt][3] = __float_as_uint(aS[(row + 8) * ASTRIDE + col + 4]); \
            }                                                                   \
            _Pragma("unroll") for (int nt = 0; nt < 8; nt++) {                  \
                int n = wn * 64 + nt * 8 + (lane >> 2);                         \
                int kc = kk * 8 + (lane & 3);                                   \
                bf[nt][0] = __float_as_uint(bS[n * ASTRIDE + kc]);              \
                bf[nt][1] = __float_as_uint(bS[n * ASTRIDE + kc + 4]);          \
            }                                                                   \
            _Pragma("unroll") for (int mt = 0; mt < 2; mt++)                    \
                _Pragma("unroll") for (int nt = 0; nt < 8; nt++)                \
                    mma8(acc[mt][nt], af[mt], bf[nt]);                          \
        }                                                                       \
    } while (0)

// ---------------------------------------------------------------------------
// Grouped projection: per group g, C[b, e] = sum_d X[b,g,d] * W[g,d,e].
// M=128 (batch), N=128-tile of e, K=1024. W slab needs transpose k-major.
// ---------------------------------------------------------------------------
__global__ void __launch_bounds__(256, 1) proj_mma(
    const float* __restrict__ X, const float* __restrict__ W, float* __restrict__ C)
{
    extern __shared__ float sm[];
    const int tid = threadIdx.x;
    const int lane = tid & 31, wid = tid >> 5;
    const int wm = wid >> 1, wn = wid & 1;
    const int g = blockIdx.y;
    const int nBase = blockIdx.x * 128;

    const float* Xg = X + (size_t)g * 1024;
    const float* Wg = W + (size_t)g * 1048576 + nBase;

    const int kr = tid >> 3;   // 0..31
    const int lc = tid & 7;

    float acc[2][8][4] = {};
    float4 aw[4], bw[4];

#define PROJ_LDG(k0)                                                           \
    do {                                                                       \
        _Pragma("unroll") for (int p = 0; p < 4; p++) {                        \
            int r = p * 32 + (tid >> 3);                                       \
            aw[p] = *(const float4*)(Xg + (size_t)r * 65536 + (k0) + lc * 4);  \
        }                                                                      \
        _Pragma("unroll") for (int j = 0; j < 4; j++)                          \
            bw[j] = *(const float4*)(Wg + (size_t)((k0) + kr) * 1024 + j * 32 + lc * 4); \
    } while (0)

#define PROJ_STS(s)                                                            \
    do {                                                                       \
        float* aS = sm + (s) * STAGE_F;                                        \
        float* bS = aS + 4608;                                                 \
        _Pragma("unroll") for (int p = 0; p < 4; p++) {                        \
            int r = p * 32 + (tid >> 3);                                       \
            *(float4*)(aS + r * ASTRIDE + lc * 4) =                            \
                make_float4(tf32r(aw[p].x), tf32r(aw[p].y),                    \
                            tf32r(aw[p].z), tf32r(aw[p].w));                   \
        }                                                                      \
        _Pragma("unroll") for (int j = 0; j < 4; j++) {                        \
            float vv[4] = {bw[j].x, bw[j].y, bw[j].z, bw[j].w};                \
            _Pragma("unroll") for (int e0 = 0; e0 < 4; e0++) {                 \
                int e = (e0 + tid) & 3;                                        \
                int n = j * 32 + lc * 4 + e;                                   \
                bS[n * ASTRIDE + kr] = tf32r(vv[e]);                           \
            }                                                                  \
        }                                                                      \
    } while (0)

    PROJ_LDG(0);
    PROJ_STS(0);
    __syncthreads();

    for (int i = 0; i < 32; i++) {
        const int s = i & 1;
        if (i < 31) PROJ_LDG((i + 1) * 32);
        GEMM_COMPUTE(s * STAGE_F);
        if (i < 31) {
            PROJ_STS(1 - s);
            __syncthreads();
        }
    }

    float* Cg = C + (size_t)g * 1024 + nBase;
#pragma unroll
    for (int mt = 0; mt < 2; mt++) {
#pragma unroll
        for (int nt = 0; nt < 8; nt++) {
            int row = wm * 32 + mt * 16 + (lane >> 2);
            int col = wn * 64 + nt * 8 + (lane & 3) * 2;
            *(float2*)(Cg + (size_t)row * 65536 + col) =
                make_float2(acc[mt][nt][0], acc[mt][nt][1]);
            *(float2*)(Cg + (size_t)(row + 8) * 65536 + col) =
                make_float2(acc[mt][nt][2], acc[mt][nt][3]);
        }
    }
#undef PROJ_LDG
#undef PROJ_STS
}

// ---------------------------------------------------------------------------
// Dense GEMM body shared by fc / gate: A [8192,1024] row-major, Wt [1024,1024]
// row-major with rows = output features (K-contiguous: direct copy staging).
// MODE 0: scr[m,n] = tanh(acc + fb[n])
// MODE 1: out[m,n] = sigmoid(acc + gb[n]) * scr[m,n]
// ---------------------------------------------------------------------------
template <int MODE>
__global__ void __launch_bounds__(256, 1) dense_mma(
    const float* __restrict__ A, const float* __restrict__ Wt,
    const float* __restrict__ bias, const float* __restrict__ scr,
    float* __restrict__ out)
{
    extern __shared__ float sm[];
    const int tid = threadIdx.x;
    const int lane = tid & 31, wid = tid >> 5;
    const int wm = wid >> 1, wn = wid & 1;
    const int mBase = blockIdx.y * 128;
    const int nBase = blockIdx.x * 128;

    const int lc = tid & 7;

    float acc[2][8][4] = {};
    float4 aw[4], bw[4];

#define DENSE_LDG(k0)                                                          \
    do {                                                                       \
        _Pragma("unroll") for (int p = 0; p < 4; p++) {                        \
            int r = p * 32 + (tid >> 3);                                       \
            aw[p] = *(const float4*)(A + (size_t)(mBase + r) * 1024 + (k0) + lc * 4); \
            bw[p] = *(const float4*)(Wt + (size_t)(nBase + r) * 1024 + (k0) + lc * 4); \
        }                                                                      \
    } while (0)

#define DENSE_STS(s)                                                           \
    do {                                                                       \
        float* aS = sm + (s) * STAGE_F;                                        \
        float* bS = aS + 4608;                                                 \
        _Pragma("unroll") for (int p = 0; p < 4; p++) {                        \
            int r = p * 32 + (tid >> 3);                                       \
            *(float4*)(aS + r * ASTRIDE + lc * 4) =                            \
                make_float4(tf32r(aw[p].x), tf32r(aw[p].y),                    \
                            tf32r(aw[p].z), tf32r(aw[p].w));                   \
            *(float4*)(bS + r * ASTRIDE + lc * 4) =                            \
                make_float4(tf32r(bw[p].x), tf32r(bw[p].y),                    \
                            tf32r(bw[p].z), tf32r(bw[p].w));                   \
        }                                                                      \
    } while (0)

    DENSE_LDG(0);
    DENSE_STS(0);
    __syncthreads();

    for (int i = 0; i < 32; i++) {
        const int s = i & 1;
        if (i < 31) DENSE_LDG((i + 1) * 32);
        GEMM_COMPUTE(s * STAGE_F);
        if (i < 31) {
            DENSE_STS(1 - s);
            __syncthreads();
        }
    }

#pragma unroll
    for (int mt = 0; mt < 2; mt++) {
#pragma unroll
        for (int nt = 0; nt < 8; nt++) {
            int row = mBase + wm * 32 + mt * 16 + (lane >> 2);
            int col = nBase + wn * 64 + nt * 8 + (lane & 3) * 2;
            float b0 = bias[col], b1 = bias[col + 1];
#pragma unroll
            for (int half = 0; half < 2; half++) {
                int r = row + half * 8;
                float v0 = acc[mt][nt][half * 2 + 0] + b0;
                float v1 = acc[mt][nt][half * 2 + 1] + b1;
                float2 o;
                if (MODE == 0) {
                    o = make_float2(tanhf(v0), tanhf(v1));
                } else {
                    float2 t = *(const float2*)(scr + (size_t)r * 1024 + col);
                    o = make_float2(t.x / (1.f + __expf(-v0)),
                                    t.y / (1.f + __expf(-v1)));
                }
                *(float2*)(out + (size_t)r * 1024 + col) = o;
            }
        }
    }
#undef DENSE_LDG
#undef DENSE_STS
}

// ---------------------------------------------------------------------------
// Attention kernel (fp32) — unchanged; 87us, not the current bottleneck.
// ---------------------------------------------------------------------------
__global__ void __launch_bounds__(256) attn_kernel(
    const float* __restrict__ qp, const float* __restrict__ kp,
    const float* __restrict__ vp, float* __restrict__ attn_out,
    float* __restrict__ ctx)
{
    __shared__ float qs[64][65];
    __shared__ float ks[64][65];

    const int bh = blockIdx.x;
    const int b = bh >> 4;
    const int h = bh & 15;
    const int tid = threadIdx.x;
    const int tx = tid & 15;
    const int ty = tid >> 4;

    const float* qbase = qp + (long)(b * 64) * 1024 + h * 64;
    const float* kbase = kp + (long)(b * 64) * 1024 + h * 64;

#pragma unroll
    for (int i = 0; i < 4; i++) {
        int f = i * 256 + tid;
        int row = f >> 4;
        int c4 = f & 15;
        float4 v = *(const float4*)(qbase + (long)row * 1024 + c4 * 4);
        qs[row][c4 * 4 + 0] = v.x; qs[row][c4 * 4 + 1] = v.y;
        qs[row][c4 * 4 + 2] = v.z; qs[row][c4 * 4 + 3] = v.w;
        float4 w = *(const float4*)(kbase + (long)row * 1024 + c4 * 4);
        ks[row][c4 * 4 + 0] = w.x; ks[row][c4 * 4 + 1] = w.y;
        ks[row][c4 * 4 + 2] = w.z; ks[row][c4 * 4 + 3] = w.w;
    }
    __syncthreads();

    float s[4][4] = {};
#pragma unroll 8
    for (int d = 0; d < 64; d++) {
        float a[4], bb[4];
#pragma unroll
        for (int i = 0; i < 4; i++) a[i] = qs[ty * 4 + i][d];
#pragma unroll
        for (int j = 0; j < 4; j++) bb[j] = ks[tx * 4 + j][d];
#pragma unroll
        for (int i = 0; i < 4; i++)
#pragma unroll
            for (int j = 0; j < 4; j++)
                s[i][j] = fmaf(a[i], bb[j], s[i][j]);
    }
    __syncthreads();

    float a[4][4];
#pragma unroll
    for (int i = 0; i < 4; i++) {
        float m = -1e30f;
#pragma unroll
        for (int j = 0; j < 4; j++) {
            s[i][j] *= 0.125f;
            m = fmaxf(m, s[i][j]);
        }
#pragma unroll
        for (int off = 8; off >= 1; off >>= 1)
            m = fmaxf(m, __shfl_xor_sync(0xffffffffu, m, off));
        float sum = 0.f;
#pragma unroll
        for (int j = 0; j < 4; j++) {
            a[i][j] = __expf(s[i][j] - m);
            sum += a[i][j];
        }
#pragma unroll
        for (int off = 8; off >= 1; off >>= 1)
            sum += __shfl_xor_sync(0xffffffffu, sum, off);
        float inv = 1.f / sum;
#pragma unroll
        for (int j = 0; j < 4; j++) a[i][j] *= inv;
    }

    float* aout = attn_out + ((long)(b * 16 + h) * 64) * 64;
#pragma unroll
    for (int i = 0; i < 4; i++) {
#pragma unroll
        for (int j = 0; j < 4; j++) qs[ty * 4 + i][tx * 4 + j] = a[i][j];
        float4 o = make_float4(a[i][0], a[i][1], a[i][2], a[i][3]);
        *(float4*)(aout + (ty * 4 + i) * 64 + tx * 4) = o;
    }

    const float* vbase = vp + (long)(b * 64) * 1024 + h * 64;
#pragma unroll
    for (int i = 0; i < 4; i++) {
        int f = i * 256 + tid;
        int row = f >> 4;
        int c4 = f & 15;
        float4 v = *(const float4*)(vbase + (long)row * 1024 + c4 * 4);
        ks[row][c4 * 4 + 0] = v.x; ks[row][c4 * 4 + 1] = v.y;
        ks[row][c4 * 4 + 2] = v.z; ks[row][c4 * 4 + 3] = v.w;
    }
    __syncthreads();

    float o[4][4] = {};
#pragma unroll 8
    for (int k = 0; k < 64; k++) {
        float av[4], bv[4];
#pragma unroll
        for (int i = 0; i < 4; i++) av[i] = qs[ty * 4 + i][k];
#pragma unroll
        for (int j = 0; j < 4; j++) bv[j] = ks[k][tx * 4 + j];
#pragma unroll
        for (int i = 0; i < 4; i++)
#pragma unroll
            for (int j = 0; j < 4; j++)
                o[i][j] = fmaf(av[i], bv[j], o[i][j]);
    }

    float* cb = ctx + (long)(b * 64) * 1024 + h * 64;
#pragma unroll
    for (int i = 0; i < 4; i++) {
        float4 v = make_float4(o[i][0], o[i][1], o[i][2], o[i][3]);
        *(float4*)(cb + (long)(ty * 4 + i) * 1024 + tx * 4) = v;
    }
}

// ---------------------------------------------------------------------------
// Launch
// ---------------------------------------------------------------------------
extern "C" void kernel_launch(void* const* d_in, const int* in_sizes, int n_in,
                              void* d_out, int out_size) {
    const float* q    = (const float*)d_in[0];
    const float* k    = (const float*)d_in[1];
    const float* v    = (const float*)d_in[2];
    const float* w_q  = (const float*)d_in[3];
    const float* w_k  = (const float*)d_in[4];
    const float* w_v  = (const float*)d_in[5];
    const float* fc_w = (const float*)d_in[6];
    const float* fc_b = (const float*)d_in[7];
    const float* g_w  = (const float*)d_in[8];
    const float* g_b  = (const float*)d_in[9];

    float* out = (float*)d_out;
    float* attn = (float*)d_out + OUT_ELEMS;

    float *qp, *kp, *vp, *ctx;
    cudaGetSymbolAddress((void**)&qp, g_qp);
    cudaGetSymbolAddress((void**)&kp, g_kp);
    cudaGetSymbolAddress((void**)&vp, g_vp);
    cudaGetSymbolAddress((void**)&ctx, g_ctx);
    float* scr = qp;  // reuse q-proj scratch after attention

    const int SMEM = 2 * STAGE_F * 4;  // 73728 bytes
    cudaFuncSetAttribute(proj_mma, cudaFuncAttributeMaxDynamicSharedMemorySize, SMEM);
    cudaFuncSetAttribute(dense_mma<0>, cudaFuncAttributeMaxDynamicSharedMemorySize, SMEM);
    cudaFuncSetAttribute(dense_mma<1>, cudaFuncAttributeMaxDynamicSharedMemorySize, SMEM);

    dim3 gp(8, 64);  // 8 N-tiles x 64 groups
    proj_mma<<<gp, 256, SMEM>>>(q, w_q, qp);
    proj_mma<<<gp, 256, SMEM>>>(k, w_k, kp);
    proj_mma<<<gp, 256, SMEM>>>(v, w_v, vp);

    attn_kernel<<<2048, 256>>>(qp, kp, vp, attn, ctx);

    dim3 gf(8, 64);  // 8 N-tiles x 64 M-tiles
    dense_mma<0><<<gf, 256, SMEM>>>(ctx, fc_w, fc_b, nullptr, scr);
    dense_mma<1><<<gf, 256, SMEM>>>(ctx, g_w, g_b, scr, out);
}